// round 16
// baseline (speedup 1.0000x reference)
#include <cuda_runtime.h>
#include <cuda_fp16.h>
#include <cstdint>
#include <cfloat>

#define BB 16
#define CH 32
#define HH 256
#define WW 256
#define NCODES 256
#define NSTEPS 5
#define HW (HH*WW)
#define NPIX (BB*HW)

__device__ float g_state[(size_t)NPIX * CH];
__device__ float g_h[(size_t)NPIX * CH];
__device__ float g_beta[(size_t)NPIX * CH];   // step-0 beta scratch
__device__ int   g_idx[NPIX];
__device__ float g_T[9 * NCODES * CH];   // conv tap tables: W_tap @ c_k
__device__ float g_B[NCODES * CH];       // beta table: sig(Wt@c_k + tau_b)
__device__ float g_declut[NCODES];       // sig(dec_w . c_k + dec_b)

// ---------- packed f32x2 helpers ----------
__device__ __forceinline__ unsigned long long pack2(float a, float b) {
    unsigned long long r;
    asm("mov.b64 %0,{%1,%2};" : "=l"(r) : "f"(a), "f"(b));
    return r;
}
__device__ __forceinline__ void unpack2(float& a, float& b, unsigned long long v) {
    asm("mov.b64 {%0,%1},%2;" : "=f"(a), "=f"(b) : "l"(v));
}
__device__ __forceinline__ void ffma2(unsigned long long& d, unsigned long long a, unsigned long long b) {
    asm("fma.rn.f32x2 %0,%1,%2,%0;" : "+l"(d) : "l"(a), "l"(b));
}
__device__ __forceinline__ void fadd2(unsigned long long& d, unsigned long long a) {
    asm("add.rn.f32x2 %0,%0,%1;" : "+l"(d) : "l"(a));
}
__device__ __forceinline__ float sigf(float x) { return 1.0f / (1.0f + __expf(-x)); }

// fp16 m16n8k16 MMA (fp32 accumulate)
__device__ __forceinline__ void mma_f16(float& d0, float& d1, float& d2, float& d3,
                                        uint32_t a0, uint32_t a1, uint32_t a2, uint32_t a3,
                                        uint32_t b0, uint32_t b1) {
    asm volatile(
        "mma.sync.aligned.m16n8k16.row.col.f32.f16.f16.f32 "
        "{%0,%1,%2,%3}, {%4,%5,%6,%7}, {%8,%9}, {%0,%1,%2,%3};"
        : "+f"(d0), "+f"(d1), "+f"(d2), "+f"(d3)
        : "r"(a0), "r"(a1), "r"(a2), "r"(a3), "r"(b0), "r"(b1));
}
// split float v -> hi/lo fp16 (lo = fp16(v - float(hi)))
__device__ __forceinline__ void split_h2(float v0, float v1, uint32_t& hi, uint32_t& lo) {
    __half h0 = __float2half_rn(v0), h1 = __float2half_rn(v1);
    __half l0 = __float2half_rn(v0 - __half2float(h0));
    __half l1 = __float2half_rn(v1 - __half2float(h1));
    hi = (uint32_t)__half_as_ushort(h0) | ((uint32_t)__half_as_ushort(h1) << 16);
    lo = (uint32_t)__half_as_ushort(l0) | ((uint32_t)__half_as_ushort(l1) << 16);
}

// ---------- build code tables ----------
__global__ __launch_bounds__(256) void build_tables_kernel(
    const float* __restrict__ up1_w, const float* __restrict__ tau_w,
    const float* __restrict__ tau_b, const float* __restrict__ cb,
    const float* __restrict__ dec_w, const float* __restrict__ dec_b)
{
    __shared__ float wsm[CH * CH];   // [oc][ic]
    int tid = threadIdx.x;
    int blk = blockIdx.x;
    if (blk < 9) {
        for (int i = tid; i < CH * CH; i += 256) wsm[i] = up1_w[i * 9 + blk];
        __syncthreads();
        float c[CH];
        const float* cr = cb + tid * CH;
#pragma unroll
        for (int i = 0; i < CH; i++) c[i] = __ldg(cr + i);
        float* out = g_T + (blk * NCODES + tid) * CH;
#pragma unroll
        for (int oc = 0; oc < CH; oc++) {
            float s = 0.0f;
            const float* wr = wsm + oc * CH;
#pragma unroll
            for (int i = 0; i < CH; i++) s += wr[i] * c[i];
            out[oc] = s;
        }
    } else {
        for (int i = tid; i < CH * CH; i += 256) wsm[i] = tau_w[i];
        __syncthreads();
        float c[CH];
        const float* cr = cb + tid * CH;
#pragma unroll
        for (int i = 0; i < CH; i++) c[i] = __ldg(cr + i);
        float* out = g_B + tid * CH;
#pragma unroll
        for (int oc = 0; oc < CH; oc++) {
            float s = 0.0f;
            const float* wr = wsm + oc * CH;
#pragma unroll
            for (int i = 0; i < CH; i++) s += wr[i] * c[i];
            out[oc] = sigf(s + __ldg(tau_b + oc));
        }
        float d = __ldg(dec_b);
#pragma unroll
        for (int i = 0; i < CH; i++) d += __ldg(dec_w + i) * c[i];
        g_declut[tid] = sigf(d);
    }
}

// ---------- stem: conv3x3 1->32 + relu ----------
__global__ __launch_bounds__(256) void stem_kernel(
    const float* __restrict__ x, const float* __restrict__ w, const float* __restrict__ b)
{
    __shared__ float ws[CH * 9];
    __shared__ float bs[CH];
    for (int i = threadIdx.x; i < CH * 9; i += 256) ws[i] = w[i];
    if (threadIdx.x < CH) bs[threadIdx.x] = b[threadIdx.x];
    __syncthreads();

    int pid = blockIdx.x * 256 + threadIdx.x;
    int xx = pid & (WW - 1);
    int yy = (pid >> 8) & (HH - 1);

    float in9[9];
#pragma unroll
    for (int ky = 0; ky < 3; ky++)
#pragma unroll
        for (int kx = 0; kx < 3; kx++) {
            int iy = yy + ky - 1, ix = xx + kx - 1;
            float v = 0.0f;
            if ((unsigned)iy < (unsigned)HH && (unsigned)ix < (unsigned)WW)
                v = __ldg(x + pid + (ky - 1) * WW + (kx - 1));
            in9[ky * 3 + kx] = v;
        }
    float acc[CH];
#pragma unroll
    for (int c = 0; c < CH; c++) acc[c] = bs[c];
#pragma unroll
    for (int t = 0; t < 9; t++) {
        float v = in9[t];
#pragma unroll
        for (int c = 0; c < CH; c++) acc[c] += v * ws[c * 9 + t];
    }
    float4* op = (float4*)(g_state + (size_t)pid * CH);
#pragma unroll
    for (int q = 0; q < 8; q++) {
        float4 o;
        o.x = fmaxf(acc[q * 4 + 0], 0.f);
        o.y = fmaxf(acc[q * 4 + 1], 0.f);
        o.z = fmaxf(acc[q * 4 + 2], 0.f);
        o.w = fmaxf(acc[q * 4 + 3], 0.f);
        op[q] = o;
    }
}

// ---------- conv3x3 32->32 + relu : g_state -> g_h (step 0, general) ----------
__global__ __launch_bounds__(128) void conv3_relu_kernel(
    const float* __restrict__ w, const float* __restrict__ bias)
{
    __shared__ __align__(16) float ws[9 * CH * CH];  // [tap][ic][oc]
    __shared__ float bs[CH];
    int tid = threadIdx.x;
    for (int i = tid; i < 9 * CH * CH; i += 128) {
        int oc = i & 31, ic = (i >> 5) & 31, tap = i >> 10;
        ws[i] = w[(oc * CH + ic) * 9 + tap];
    }
    if (tid < CH) bs[tid] = bias[tid];
    __syncthreads();

    int quarter = tid & 3;
    int og = tid >> 2;
    int pix0 = (blockIdx.x * 32 + og) * 8;
    int x0 = pix0 & (WW - 1);
    int yy = (pix0 >> 8) & (HH - 1);
    int oc0 = quarter * 8;

    unsigned long long acc[8][4];
#pragma unroll
    for (int p = 0; p < 8; p++)
#pragma unroll
        for (int m = 0; m < 4; m++)
            acc[p][m] = pack2(bs[oc0 + 2 * m], bs[oc0 + 2 * m + 1]);

#pragma unroll
    for (int ky = 0; ky < 3; ky++) {
        int iy = yy + ky - 1;
        if ((unsigned)iy >= (unsigned)HH) continue;
        const float* rowbase = g_state + ((size_t)pix0 + (ky - 1) * WW) * CH;
#pragma unroll 1
        for (int ic4 = 0; ic4 < 8; ic4++) {
            float4 in10[10];
#pragma unroll
            for (int p = 0; p < 10; p++) {
                int ix = x0 + p - 1;
                float4 v = make_float4(0.f, 0.f, 0.f, 0.f);
                if ((unsigned)ix < (unsigned)WW)
                    v = __ldg((const float4*)(rowbase + (p - 1) * CH) + ic4);
                in10[p] = v;
            }
#pragma unroll
            for (int kx = 0; kx < 3; kx++) {
                const float* wrow = ws + (ky * 3 + kx) * (CH * CH) + oc0;
#pragma unroll
                for (int j = 0; j < 4; j++) {
                    int ic = ic4 * 4 + j;
                    const ulonglong2* wp = (const ulonglong2*)(wrow + ic * CH);
                    ulonglong2 wa = wp[0];
                    ulonglong2 wb = wp[1];
#pragma unroll
                    for (int p = 0; p < 8; p++) {
                        float v;
                        if (j == 0) v = in10[p + kx].x;
                        else if (j == 1) v = in10[p + kx].y;
                        else if (j == 2) v = in10[p + kx].z;
                        else v = in10[p + kx].w;
                        unsigned long long vp = pack2(v, v);
                        ffma2(acc[p][0], vp, wa.x);
                        ffma2(acc[p][1], vp, wa.y);
                        ffma2(acc[p][2], vp, wb.x);
                        ffma2(acc[p][3], vp, wb.y);
                    }
                }
            }
        }
    }
#pragma unroll
    for (int p = 0; p < 8; p++) {
        float4* op = (float4*)(g_h + ((size_t)pix0 + p) * CH + oc0);
#pragma unroll
        for (int q = 0; q < 2; q++) {
            float a, b;
            unpack2(a, b, acc[p][2 * q]);
            float c, d;
            unpack2(c, d, acc[p][2 * q + 1]);
            float4 o;
            o.x = fmaxf(a, 0.f); o.y = fmaxf(b, 0.f);
            o.z = fmaxf(c, 0.f); o.w = fmaxf(d, 0.f);
            op[q] = o;
        }
    }
}

// ---------- conv3x3 via code tables (steps 1..4), f32x2 adds ----------
__global__ __launch_bounds__(256) void conv_idx_kernel(const float* __restrict__ bias)
{
    __shared__ float bs[CH];
    int tid = threadIdx.x;
    if (tid < CH) bs[tid] = bias[tid];
    __syncthreads();

    int pid = blockIdx.x * 256 + tid;
    int xx = pid & (WW - 1);
    int yy = (pid >> 8) & (HH - 1);

    int nidx[9];
#pragma unroll
    for (int ky = 0; ky < 3; ky++)
#pragma unroll
        for (int kx = 0; kx < 3; kx++) {
            int iy = yy + ky - 1, ix = xx + kx - 1;
            int v = -1;
            if ((unsigned)iy < (unsigned)HH && (unsigned)ix < (unsigned)WW)
                v = __ldg(g_idx + pid + (ky - 1) * WW + (kx - 1));
            nidx[ky * 3 + kx] = v;
        }

    unsigned long long acc[16];
#pragma unroll
    for (int m = 0; m < 16; m++) acc[m] = pack2(bs[2 * m], bs[2 * m + 1]);

#pragma unroll
    for (int t = 0; t < 9; t++) {
        if (nidx[t] < 0) continue;
        const ulonglong2* tp = (const ulonglong2*)(g_T + (size_t)(t * NCODES + nidx[t]) * CH);
#pragma unroll
        for (int q = 0; q < 8; q++) {
            ulonglong2 v = __ldg(tp + q);
            fadd2(acc[2 * q], v.x);
            fadd2(acc[2 * q + 1], v.y);
        }
    }

    float4* op = (float4*)(g_h + (size_t)pid * CH);
#pragma unroll
    for (int q = 0; q < 8; q++) {
        float a, b, c, d;
        unpack2(a, b, acc[2 * q]);
        unpack2(c, d, acc[2 * q + 1]);
        float4 o;
        o.x = fmaxf(a, 0.f); o.y = fmaxf(b, 0.f);
        o.z = fmaxf(c, 0.f); o.w = fmaxf(d, 0.f);
        op[q] = o;
    }
}

// ---------- step-0 phase 1: beta = sig(Wt@s + bt) -> g_beta (2 px/thread) ----------
__global__ __launch_bounds__(256) void tau_beta_kernel(
    const float* __restrict__ wtg, const float* __restrict__ btg)
{
    __shared__ __align__(16) float wtt[CH * CH];  // [ic][oc]
    __shared__ float bts[CH];
    int tid = threadIdx.x;
    for (int i = tid; i < CH * CH; i += 256) {
        int oc = i & 31, ic = i >> 5;
        wtt[i] = wtg[oc * CH + ic];
    }
    if (tid < CH) bts[tid] = btg[tid];
    __syncthreads();

    int p0 = blockIdx.x * 512 + tid;
    int p1 = p0 + 256;
    const float4* s0 = (const float4*)(g_state + (size_t)p0 * CH);
    const float4* s1 = (const float4*)(g_state + (size_t)p1 * CH);

    unsigned long long t0a[16], t1a[16];
#pragma unroll
    for (int q = 0; q < 16; q++) {
        t0a[q] = pack2(bts[2 * q], bts[2 * q + 1]);
        t1a[q] = t0a[q];
    }
    const ulonglong2* wtv = (const ulonglong2*)wtt;
#pragma unroll
    for (int q = 0; q < 8; q++) {
        float4 a = __ldg(s0 + q);
        float4 b = __ldg(s1 + q);
        float a4[4] = {a.x, a.y, a.z, a.w};
        float b4[4] = {b.x, b.y, b.z, b.w};
#pragma unroll
        for (int j = 0; j < 4; j++) {
            int ic = q * 4 + j;
            unsigned long long va = pack2(a4[j], a4[j]);
            unsigned long long vb = pack2(b4[j], b4[j]);
            const ulonglong2* wr = wtv + ic * 8;
#pragma unroll
            for (int p = 0; p < 8; p++) {
                ulonglong2 w = wr[p];
                ffma2(t0a[2 * p], va, w.x);
                ffma2(t0a[2 * p + 1], va, w.y);
                ffma2(t1a[2 * p], vb, w.x);
                ffma2(t1a[2 * p + 1], vb, w.y);
            }
        }
    }
    float4* b0 = (float4*)(g_beta + (size_t)p0 * CH);
    float4* b1 = (float4*)(g_beta + (size_t)p1 * CH);
#pragma unroll
    for (int q = 0; q < 8; q++) {
        float u0, v0, u1, v1;
        unpack2(u0, v0, t0a[2 * q]);
        unpack2(u1, v1, t0a[2 * q + 1]);
        b0[q] = make_float4(sigf(u0), sigf(v0), sigf(u1), sigf(v1));
        unpack2(u0, v0, t1a[2 * q]);
        unpack2(u1, v1, t1a[2 * q + 1]);
        b1[q] = make_float4(sigf(u0), sigf(v0), sigf(u1), sigf(v1));
    }
}

// ---------- step-0 phase 2: z = d + beta*(s-d), d = W2@h + b2 (2 px/thread) ----------
__global__ __launch_bounds__(256) void blend2_kernel(
    const float* __restrict__ w2g, const float* __restrict__ b2g)
{
    __shared__ __align__(16) float w2t[CH * CH];  // [ic][oc]
    __shared__ float b2s[CH];
    int tid = threadIdx.x;
    for (int i = tid; i < CH * CH; i += 256) {
        int oc = i & 31, ic = i >> 5;
        w2t[i] = w2g[oc * CH + ic];
    }
    if (tid < CH) b2s[tid] = b2g[tid];
    __syncthreads();

    int p0 = blockIdx.x * 512 + tid;
    int p1 = p0 + 256;
    const float4* h0 = (const float4*)(g_h + (size_t)p0 * CH);
    const float4* h1 = (const float4*)(g_h + (size_t)p1 * CH);

    unsigned long long d0a[16], d1a[16];
#pragma unroll
    for (int q = 0; q < 16; q++) {
        d0a[q] = pack2(b2s[2 * q], b2s[2 * q + 1]);
        d1a[q] = d0a[q];
    }
    const ulonglong2* w2v = (const ulonglong2*)w2t;
#pragma unroll
    for (int q = 0; q < 8; q++) {
        float4 a = __ldg(h0 + q);
        float4 b = __ldg(h1 + q);
        float a4[4] = {a.x, a.y, a.z, a.w};
        float b4[4] = {b.x, b.y, b.z, b.w};
#pragma unroll
        for (int j = 0; j < 4; j++) {
            int ic = q * 4 + j;
            unsigned long long va = pack2(a4[j], a4[j]);
            unsigned long long vb = pack2(b4[j], b4[j]);
            const ulonglong2* wr = w2v + ic * 8;
#pragma unroll
            for (int p = 0; p < 8; p++) {
                ulonglong2 w = wr[p];
                ffma2(d0a[2 * p], va, w.x);
                ffma2(d0a[2 * p + 1], va, w.y);
                ffma2(d1a[2 * p], vb, w.x);
                ffma2(d1a[2 * p + 1], vb, w.y);
            }
        }
    }

    {
        const float4* sp = (const float4*)(g_state + (size_t)p0 * CH);
        const float4* bp = (const float4*)(g_beta + (size_t)p0 * CH);
        float4* zo = (float4*)(g_h + (size_t)p0 * CH);
#pragma unroll
        for (int q = 0; q < 8; q++) {
            float4 sv = __ldg(sp + q);
            float4 be = __ldg(bp + q);
            float e0, e1, e2, e3;
            unpack2(e0, e1, d0a[2 * q]);
            unpack2(e2, e3, d0a[2 * q + 1]);
            float4 o;
            o.x = e0 + be.x * (sv.x - e0);
            o.y = e1 + be.y * (sv.y - e1);
            o.z = e2 + be.z * (sv.z - e2);
            o.w = e3 + be.w * (sv.w - e3);
            zo[q] = o;
        }
    }
    {
        const float4* sp = (const float4*)(g_state + (size_t)p1 * CH);
        const float4* bp = (const float4*)(g_beta + (size_t)p1 * CH);
        float4* zo = (float4*)(g_h + (size_t)p1 * CH);
#pragma unroll
        for (int q = 0; q < 8; q++) {
            float4 sv = __ldg(sp + q);
            float4 be = __ldg(bp + q);
            float e0, e1, e2, e3;
            unpack2(e0, e1, d1a[2 * q]);
            unpack2(e2, e3, d1a[2 * q + 1]);
            float4 o;
            o.x = e0 + be.x * (sv.x - e0);
            o.y = e1 + be.y * (sv.y - e1);
            o.z = e2 + be.z * (sv.z - e2);
            o.w = e3 + be.w * (sv.w - e3);
            zo[q] = o;
        }
    }
}

// ---------- blend via beta table (steps 1..4), 2 pixels/thread ----------
__global__ __launch_bounds__(256) void blend_idx_kernel(
    const float* __restrict__ w2g, const float* __restrict__ b2g,
    const float* __restrict__ cb)
{
    __shared__ __align__(16) float w2t[CH * CH];  // [ic][oc]
    __shared__ float b2s[CH];
    int tid = threadIdx.x;
    for (int i = tid; i < CH * CH; i += 256) {
        int oc = i & 31, ic = i >> 5;
        w2t[i] = w2g[oc * CH + ic];
    }
    if (tid < CH) b2s[tid] = b2g[tid];
    __syncthreads();

    int p0 = blockIdx.x * 512 + tid;
    int p1 = p0 + 256;
    const float4* h0 = (const float4*)(g_h + (size_t)p0 * CH);
    const float4* h1 = (const float4*)(g_h + (size_t)p1 * CH);

    unsigned long long d0a[16], d1a[16];
#pragma unroll
    for (int q = 0; q < 16; q++) {
        d0a[q] = pack2(b2s[2 * q], b2s[2 * q + 1]);
        d1a[q] = d0a[q];
    }
    const ulonglong2* w2v = (const ulonglong2*)w2t;
#pragma unroll
    for (int q = 0; q < 8; q++) {
        float4 a = __ldg(h0 + q);
        float4 b = __ldg(h1 + q);
        float a4[4] = {a.x, a.y, a.z, a.w};
        float b4[4] = {b.x, b.y, b.z, b.w};
#pragma unroll
        for (int j = 0; j < 4; j++) {
            int ic = q * 4 + j;
            unsigned long long va = pack2(a4[j], a4[j]);
            unsigned long long vb = pack2(b4[j], b4[j]);
            const ulonglong2* wr = w2v + ic * 8;
#pragma unroll
            for (int p = 0; p < 8; p++) {
                ulonglong2 w = wr[p];
                ffma2(d0a[2 * p], va, w.x);
                ffma2(d0a[2 * p + 1], va, w.y);
                ffma2(d1a[2 * p], vb, w.x);
                ffma2(d1a[2 * p + 1], vb, w.y);
            }
        }
    }

    {
        int idx = __ldg(g_idx + p0);
        const float4* bp = (const float4*)(g_B + (size_t)idx * CH);
        const float4* sp = (const float4*)(cb + (size_t)idx * CH);
        float4* zo = (float4*)(g_h + (size_t)p0 * CH);
#pragma unroll
        for (int q = 0; q < 8; q++) {
            float4 be = __ldg(bp + q);
            float4 sv = __ldg(sp + q);
            float e0, e1, e2, e3;
            unpack2(e0, e1, d0a[2 * q]);
            unpack2(e2, e3, d0a[2 * q + 1]);
            float4 o;
            o.x = e0 + be.x * (sv.x - e0);
            o.y = e1 + be.y * (sv.y - e1);
            o.z = e2 + be.z * (sv.z - e2);
            o.w = e3 + be.w * (sv.w - e3);
            zo[q] = o;
        }
    }
    {
        int idx = __ldg(g_idx + p1);
        const float4* bp = (const float4*)(g_B + (size_t)idx * CH);
        const float4* sp = (const float4*)(cb + (size_t)idx * CH);
        float4* zo = (float4*)(g_h + (size_t)p1 * CH);
#pragma unroll
        for (int q = 0; q < 8; q++) {
            float4 be = __ldg(bp + q);
            float4 sv = __ldg(sp + q);
            float e0, e1, e2, e3;
            unpack2(e0, e1, d1a[2 * q]);
            unpack2(e2, e3, d1a[2 * q + 1]);
            float4 o;
            o.x = e0 + be.x * (sv.x - e0);
            o.y = e1 + be.y * (sv.y - e1);
            o.z = e2 + be.z * (sv.z - e2);
            o.w = e3 + be.w * (sv.w - e3);
            zo[q] = o;
        }
    }
}

// ---------- VQ via mma.sync f16 m16n8k16, 3-pass split (hh+lh+hl), B scaled 256 ----------
#define BSTR16 20

__global__ __launch_bounds__(256) void vq_mma_kernel(const float* __restrict__ cb)
{
    __shared__ uint32_t sBh[NCODES * BSTR16];  // hi half2 per (col, k2)
    __shared__ uint32_t sBl[NCODES * BSTR16];  // lo half2
    __shared__ float cn[NCODES];
    int tid = threadIdx.x;

    for (int i = tid; i < NCODES * 16; i += 256) {
        int code = i >> 4, k2 = i & 15;
        const float2 v = __ldg((const float2*)(cb + code * CH + 2 * k2));
        uint32_t hi, lo;
        split_h2(v.x * 256.0f, v.y * 256.0f, hi, lo);
        sBh[code * BSTR16 + k2] = hi;
        sBl[code * BSTR16 + k2] = lo;
    }
    {
        float s = 0.0f;
        const float* cr = cb + tid * CH;
#pragma unroll
        for (int c = 0; c < CH; c++) { float v = __ldg(cr + c); s += v * v; }
        cn[tid] = 128.0f * s;
    }
    __syncthreads();

    int wid = tid >> 5, lid = tid & 31;
    int kq = lid & 3;
    int colb = lid >> 2;

#pragma unroll 1
    for (int tile = 0; tile < 2; tile++) {
        int rbase = blockIdx.x * 512 + tile * 256 + wid * 32 + (lid >> 2);

        uint32_t zh[4][4], zl[4][4];
#pragma unroll
        for (int rr = 0; rr < 4; rr++) {
            const float* z = g_h + (size_t)(rbase + 8 * rr) * CH;
#pragma unroll
            for (int j = 0; j < 4; j++) {
                float2 v = __ldg((const float2*)(z + 8 * j + 2 * kq));
                split_h2(v.x, v.y, zh[rr][j], zl[rr][j]);
            }
        }

        float best[4] = {FLT_MAX, FLT_MAX, FLT_MAX, FLT_MAX};
        int bi[4] = {0, 0, 0, 0};

#pragma unroll 1
        for (int chunk = 0; chunk < 8; chunk++) {
#pragma unroll
            for (int nt = 0; nt < 4; nt++) {
                int col = chunk * 32 + nt * 8 + colb;
                const uint32_t* bhp = sBh + col * BSTR16;
                const uint32_t* blp = sBl + col * BSTR16;
                uint32_t bh0 = bhp[kq],     bh1 = bhp[kq + 4];
                uint32_t bh2 = bhp[kq + 8], bh3 = bhp[kq + 12];
                uint32_t bl0 = blp[kq],     bl1 = blp[kq + 4];
                uint32_t bl2 = blp[kq + 8], bl3 = blp[kq + 12];

                float dA0 = 0.f, dA1 = 0.f, dA2 = 0.f, dA3 = 0.f;
                float dB0 = 0.f, dB1 = 0.f, dB2 = 0.f, dB3 = 0.f;
                mma_f16(dA0, dA1, dA2, dA3, zh[0][0], zh[1][0], zh[0][1], zh[1][1], bh0, bh1);
                mma_f16(dA0, dA1, dA2, dA3, zh[0][2], zh[1][2], zh[0][3], zh[1][3], bh2, bh3);
                mma_f16(dA0, dA1, dA2, dA3, zl[0][0], zl[1][0], zl[0][1], zl[1][1], bh0, bh1);
                mma_f16(dA0, dA1, dA2, dA3, zl[0][2], zl[1][2], zl[0][3], zl[1][3], bh2, bh3);
                mma_f16(dA0, dA1, dA2, dA3, zh[0][0], zh[1][0], zh[0][1], zh[1][1], bl0, bl1);
                mma_f16(dA0, dA1, dA2, dA3, zh[0][2], zh[1][2], zh[0][3], zh[1][3], bl2, bl3);
                mma_f16(dB0, dB1, dB2, dB3, zh[2][0], zh[3][0], zh[2][1], zh[3][1], bh0, bh1);
                mma_f16(dB0, dB1, dB2, dB3, zh[2][2], zh[3][2], zh[2][3], zh[3][3], bh2, bh3);
                mma_f16(dB0, dB1, dB2, dB3, zl[2][0], zl[3][0], zl[2][1], zl[3][1], bh0, bh1);
                mma_f16(dB0, dB1, dB2, dB3, zl[2][2], zl[3][2], zl[2][3], zl[3][3], bh2, bh3);
                mma_f16(dB0, dB1, dB2, dB3, zh[2][0], zh[3][0], zh[2][1], zh[3][1], bl0, bl1);
                mma_f16(dB0, dB1, dB2, dB3, zh[2][2], zh[3][2], zh[2][3], zh[3][3], bl2, bl3);

                int c0 = chunk * 32 + nt * 8 + 2 * kq;
                float cna = cn[c0], cnb = cn[c0 + 1];
                float m;
                m = cna - dA0; if (m < best[0]) { best[0] = m; bi[0] = c0; }
                m = cnb - dA1; if (m < best[0]) { best[0] = m; bi[0] = c0 + 1; }
                m = cna - dA2; if (m < best[1]) { best[1] = m; bi[1] = c0; }
                m = cnb - dA3; if (m < best[1]) { best[1] = m; bi[1] = c0 + 1; }
                m = cna - dB0; if (m < best[2]) { best[2] = m; bi[2] = c0; }
                m = cnb - dB1; if (m < best[2]) { best[2] = m; bi[2] = c0 + 1; }
                m = cna - dB2; if (m < best[3]) { best[3] = m; bi[3] = c0; }
                m = cnb - dB3; if (m < best[3]) { best[3] = m; bi[3] = c0 + 1; }
            }
        }

#pragma unroll
        for (int off = 1; off <= 2; off <<= 1) {
#pragma unroll
            for (int rr = 0; rr < 4; rr++) {
                float ob = __shfl_xor_sync(0xffffffffu, best[rr], off);
                int oi = __shfl_xor_sync(0xffffffffu, bi[rr], off);
                if (ob < best[rr] || (ob == best[rr] && oi < bi[rr])) { best[rr] = ob; bi[rr] = oi; }
            }
        }

        if ((lid & 3) == 0) {
#pragma unroll
            for (int rr = 0; rr < 4; rr++)
                g_idx[rbase + 8 * rr] = bi[rr];
        }
    }
}

// ---------- decoder via LUT ----------
__global__ __launch_bounds__(256) void dec_idx_kernel(float* __restrict__ out)
{
    __shared__ float lut[NCODES];
    lut[threadIdx.x] = g_declut[threadIdx.x];
    __syncthreads();
    int pid = blockIdx.x * 256 + threadIdx.x;
    out[pid] = lut[__ldg(g_idx + pid)];
}

extern "C" void kernel_launch(void* const* d_in, const int* in_sizes, int n_in,
                              void* d_out, int out_size)
{
    const float* x      = (const float*)d_in[0];
    const float* stem_w = (const float*)d_in[1];
    const float* stem_b = (const float*)d_in[2];
    const float* up1_w  = (const float*)d_in[3];
    const float* up1_b  = (const float*)d_in[4];
    const float* up2_w  = (const float*)d_in[5];
    const float* up2_b  = (const float*)d_in[6];
    const float* tau_w  = (const float*)d_in[7];
    const float* tau_b  = (const float*)d_in[8];
    const float* cb     = (const float*)d_in[9];
    const float* dec_w  = (const float*)d_in[10];
    const float* dec_b  = (const float*)d_in[11];

    build_tables_kernel<<<10, 256>>>(up1_w, tau_w, tau_b, cb, dec_w, dec_b);
    stem_kernel<<<NPIX / 256, 256>>>(x, stem_w, stem_b);

    // step 0: general path (state not yet quantized)
    conv3_relu_kernel<<<NPIX / 256, 128>>>(up1_w, up1_b);
    tau_beta_kernel<<<NPIX / 512, 256>>>(tau_w, tau_b);
    blend2_kernel<<<NPIX / 512, 256>>>(up2_w, up2_b);
    vq_mma_kernel<<<NPIX / 512, 256>>>(cb);

    // steps 1..4: table path (split kernels — fusion loses, see R11)
    for (int t = 1; t < NSTEPS; t++) {
        conv_idx_kernel<<<NPIX / 256, 256>>>(up1_b);
        blend_idx_kernel<<<NPIX / 512, 256>>>(up2_w, up2_b, cb);
        vq_mma_kernel<<<NPIX / 512, 256>>>(cb);
    }
    dec_idx_kernel<<<NPIX / 256, 256>>>((float*)d_out);
}

// round 17
// speedup vs baseline: 1.0649x; 1.0649x over previous
#include <cuda_runtime.h>
#include <cuda_fp16.h>
#include <cstdint>
#include <cfloat>

#define BB 16
#define CH 32
#define HH 256
#define WW 256
#define NCODES 256
#define NSTEPS 5
#define HW (HH*WW)
#define NPIX (BB*HW)

__device__ float g_state[(size_t)NPIX * CH];
__device__ float g_h[(size_t)NPIX * CH];
__device__ int   g_idx[NPIX];
__device__ float g_T[9 * NCODES * CH];   // conv tap tables: W_tap @ c_k
__device__ float g_B[NCODES * CH];       // beta table: sig(Wt@c_k + tau_b)
__device__ float g_declut[NCODES];       // sig(dec_w . c_k + dec_b)

// ---------- packed f32x2 helpers ----------
__device__ __forceinline__ unsigned long long pack2(float a, float b) {
    unsigned long long r;
    asm("mov.b64 %0,{%1,%2};" : "=l"(r) : "f"(a), "f"(b));
    return r;
}
__device__ __forceinline__ void unpack2(float& a, float& b, unsigned long long v) {
    asm("mov.b64 {%0,%1},%2;" : "=f"(a), "=f"(b) : "l"(v));
}
__device__ __forceinline__ void ffma2(unsigned long long& d, unsigned long long a, unsigned long long b) {
    asm("fma.rn.f32x2 %0,%1,%2,%0;" : "+l"(d) : "l"(a), "l"(b));
}
__device__ __forceinline__ void fadd2(unsigned long long& d, unsigned long long a) {
    asm("add.rn.f32x2 %0,%0,%1;" : "+l"(d) : "l"(a));
}
__device__ __forceinline__ float sigf(float x) { return 1.0f / (1.0f + __expf(-x)); }

// fp16 m16n8k16 MMA (fp32 accumulate)
__device__ __forceinline__ void mma_f16(float& d0, float& d1, float& d2, float& d3,
                                        uint32_t a0, uint32_t a1, uint32_t a2, uint32_t a3,
                                        uint32_t b0, uint32_t b1) {
    asm volatile(
        "mma.sync.aligned.m16n8k16.row.col.f32.f16.f16.f32 "
        "{%0,%1,%2,%3}, {%4,%5,%6,%7}, {%8,%9}, {%0,%1,%2,%3};"
        : "+f"(d0), "+f"(d1), "+f"(d2), "+f"(d3)
        : "r"(a0), "r"(a1), "r"(a2), "r"(a3), "r"(b0), "r"(b1));
}
// split float v -> hi/lo fp16 (lo = fp16(v - float(hi)))
__device__ __forceinline__ void split_h2(float v0, float v1, uint32_t& hi, uint32_t& lo) {
    __half h0 = __float2half_rn(v0), h1 = __float2half_rn(v1);
    __half l0 = __float2half_rn(v0 - __half2float(h0));
    __half l1 = __float2half_rn(v1 - __half2float(h1));
    hi = (uint32_t)__half_as_ushort(h0) | ((uint32_t)__half_as_ushort(h1) << 16);
    lo = (uint32_t)__half_as_ushort(l0) | ((uint32_t)__half_as_ushort(l1) << 16);
}

// ---------- build code tables ----------
__global__ __launch_bounds__(256) void build_tables_kernel(
    const float* __restrict__ up1_w, const float* __restrict__ tau_w,
    const float* __restrict__ tau_b, const float* __restrict__ cb,
    const float* __restrict__ dec_w, const float* __restrict__ dec_b)
{
    __shared__ float wsm[CH * CH];   // [oc][ic]
    int tid = threadIdx.x;
    int blk = blockIdx.x;
    if (blk < 9) {
        for (int i = tid; i < CH * CH; i += 256) wsm[i] = up1_w[i * 9 + blk];
        __syncthreads();
        float c[CH];
        const float* cr = cb + tid * CH;
#pragma unroll
        for (int i = 0; i < CH; i++) c[i] = __ldg(cr + i);
        float* out = g_T + (blk * NCODES + tid) * CH;
#pragma unroll
        for (int oc = 0; oc < CH; oc++) {
            float s = 0.0f;
            const float* wr = wsm + oc * CH;
#pragma unroll
            for (int i = 0; i < CH; i++) s += wr[i] * c[i];
            out[oc] = s;
        }
    } else {
        for (int i = tid; i < CH * CH; i += 256) wsm[i] = tau_w[i];
        __syncthreads();
        float c[CH];
        const float* cr = cb + tid * CH;
#pragma unroll
        for (int i = 0; i < CH; i++) c[i] = __ldg(cr + i);
        float* out = g_B + tid * CH;
#pragma unroll
        for (int oc = 0; oc < CH; oc++) {
            float s = 0.0f;
            const float* wr = wsm + oc * CH;
#pragma unroll
            for (int i = 0; i < CH; i++) s += wr[i] * c[i];
            out[oc] = sigf(s + __ldg(tau_b + oc));
        }
        float d = __ldg(dec_b);
#pragma unroll
        for (int i = 0; i < CH; i++) d += __ldg(dec_w + i) * c[i];
        g_declut[tid] = sigf(d);
    }
}

// ---------- stem: conv3x3 1->32 + relu ----------
__global__ __launch_bounds__(256) void stem_kernel(
    const float* __restrict__ x, const float* __restrict__ w, const float* __restrict__ b)
{
    __shared__ float ws[CH * 9];
    __shared__ float bs[CH];
    for (int i = threadIdx.x; i < CH * 9; i += 256) ws[i] = w[i];
    if (threadIdx.x < CH) bs[threadIdx.x] = b[threadIdx.x];
    __syncthreads();

    int pid = blockIdx.x * 256 + threadIdx.x;
    int xx = pid & (WW - 1);
    int yy = (pid >> 8) & (HH - 1);

    float in9[9];
#pragma unroll
    for (int ky = 0; ky < 3; ky++)
#pragma unroll
        for (int kx = 0; kx < 3; kx++) {
            int iy = yy + ky - 1, ix = xx + kx - 1;
            float v = 0.0f;
            if ((unsigned)iy < (unsigned)HH && (unsigned)ix < (unsigned)WW)
                v = __ldg(x + pid + (ky - 1) * WW + (kx - 1));
            in9[ky * 3 + kx] = v;
        }
    float acc[CH];
#pragma unroll
    for (int c = 0; c < CH; c++) acc[c] = bs[c];
#pragma unroll
    for (int t = 0; t < 9; t++) {
        float v = in9[t];
#pragma unroll
        for (int c = 0; c < CH; c++) acc[c] += v * ws[c * 9 + t];
    }
    float4* op = (float4*)(g_state + (size_t)pid * CH);
#pragma unroll
    for (int q = 0; q < 8; q++) {
        float4 o;
        o.x = fmaxf(acc[q * 4 + 0], 0.f);
        o.y = fmaxf(acc[q * 4 + 1], 0.f);
        o.z = fmaxf(acc[q * 4 + 2], 0.f);
        o.w = fmaxf(acc[q * 4 + 3], 0.f);
        op[q] = o;
    }
}

// ---------- step-0 conv3x3 32->32 + relu via fp16 MMA (3-pass split) ----------
// Warp = m16 tile (16 consecutive pixels, same image row). Per tap: shifted A
// fragments, B = presplit weights in smem (stride 17, conflict-free).
#define WSTR17 17

__global__ __launch_bounds__(256) void conv3_mma_kernel(
    const float* __restrict__ w, const float* __restrict__ bias)
{
    __shared__ uint32_t sWh[9 * 32 * WSTR17];
    __shared__ uint32_t sWl[9 * 32 * WSTR17];
    __shared__ float bs[CH];
    int tid = threadIdx.x;
    // weights: B[tap][oc][k2] = half2(w[oc][2k2][tap], w[oc][2k2+1][tap])
    for (int i = tid; i < 9 * 32 * 16; i += 256) {
        int k2 = i & 15, oc = (i >> 4) & 31, tap = i >> 9;
        float v0 = __ldg(w + (oc * CH + 2 * k2) * 9 + tap);
        float v1 = __ldg(w + (oc * CH + 2 * k2 + 1) * 9 + tap);
        uint32_t hi, lo;
        split_h2(v0, v1, hi, lo);
        int off = (tap * 32 + oc) * WSTR17 + k2;
        sWh[off] = hi;
        sWl[off] = lo;
    }
    if (tid < CH) bs[tid] = bias[tid];
    __syncthreads();

    int wid = tid >> 5, lid = tid & 31;
    int kq = lid & 3;
    int colb = lid >> 2;            // A-row within tile / B-col within n8
    int pix0 = (blockIdx.x * 8 + wid) * 16;
    int x0 = pix0 & (WW - 1);
    int y = (pix0 >> 8) & (HH - 1);

    float acc[4][4];                 // [nt][d0..d3]
#pragma unroll
    for (int nt = 0; nt < 4; nt++)
#pragma unroll
        for (int d = 0; d < 4; d++) acc[nt][d] = 0.f;

#pragma unroll 1
    for (int tap = 0; tap < 9; tap++) {
        int dy = tap / 3 - 1, dx = tap % 3 - 1;
        int iy = y + dy;
        bool rowok = (unsigned)iy < (unsigned)HH;

        // A fragments: [slot][q]; q0: k=2kq, q1: k=2kq+8, q2: k=16+2kq, q3: k=24+2kq
        uint32_t Ah[2][4], Al[2][4];
#pragma unroll
        for (int slot = 0; slot < 2; slot++) {
            int r = colb + 8 * slot;
            int ix = x0 + r + dx;
            bool ok = rowok && (unsigned)ix < (unsigned)WW;
            const float* p = g_state + ((size_t)pix0 + r + dy * WW + dx) * CH;
#pragma unroll
            for (int q = 0; q < 4; q++) {
                int k = ((q & 1) << 3) + ((q >> 1) << 4) + 2 * kq;
                float2 v = make_float2(0.f, 0.f);
                if (ok) v = __ldg((const float2*)(p + k));
                split_h2(v.x, v.y, Ah[slot][q], Al[slot][q]);
            }
        }

#pragma unroll
        for (int nt = 0; nt < 4; nt++) {
            const uint32_t* bh = sWh + (tap * 32 + nt * 8 + colb) * WSTR17;
            const uint32_t* bl = sWl + (tap * 32 + nt * 8 + colb) * WSTR17;
            // kstep 0 (ic 0..15)
            uint32_t b0 = bh[kq], b1 = bh[kq + 4];
            uint32_t c0 = bl[kq], c1 = bl[kq + 4];
            mma_f16(acc[nt][0], acc[nt][1], acc[nt][2], acc[nt][3],
                    Ah[0][0], Ah[1][0], Ah[0][1], Ah[1][1], b0, b1);
            mma_f16(acc[nt][0], acc[nt][1], acc[nt][2], acc[nt][3],
                    Al[0][0], Al[1][0], Al[0][1], Al[1][1], b0, b1);
            mma_f16(acc[nt][0], acc[nt][1], acc[nt][2], acc[nt][3],
                    Ah[0][0], Ah[1][0], Ah[0][1], Ah[1][1], c0, c1);
            // kstep 1 (ic 16..31)
            uint32_t b2 = bh[kq + 8], b3 = bh[kq + 12];
            uint32_t c2 = bl[kq + 8], c3 = bl[kq + 12];
            mma_f16(acc[nt][0], acc[nt][1], acc[nt][2], acc[nt][3],
                    Ah[0][2], Ah[1][2], Ah[0][3], Ah[1][3], b2, b3);
            mma_f16(acc[nt][0], acc[nt][1], acc[nt][2], acc[nt][3],
                    Al[0][2], Al[1][2], Al[0][3], Al[1][3], b2, b3);
            mma_f16(acc[nt][0], acc[nt][1], acc[nt][2], acc[nt][3],
                    Ah[0][2], Ah[1][2], Ah[0][3], Ah[1][3], c2, c3);
        }
    }

    // epilogue: bias + relu; acc[nt] covers cols nt*8 + 2kq, +1 of rows colb, colb+8
#pragma unroll
    for (int nt = 0; nt < 4; nt++) {
        int c0 = nt * 8 + 2 * kq;
        float b0 = bs[c0], b1 = bs[c0 + 1];
        float2 o0, o1;
        o0.x = fmaxf(acc[nt][0] + b0, 0.f);
        o0.y = fmaxf(acc[nt][1] + b1, 0.f);
        o1.x = fmaxf(acc[nt][2] + b0, 0.f);
        o1.y = fmaxf(acc[nt][3] + b1, 0.f);
        *(float2*)(g_h + ((size_t)pix0 + colb) * CH + c0) = o0;
        *(float2*)(g_h + ((size_t)pix0 + colb + 8) * CH + c0) = o1;
    }
}

// ---------- conv3x3 via code tables (steps 1..4), f32x2 adds ----------
__global__ __launch_bounds__(256) void conv_idx_kernel(const float* __restrict__ bias)
{
    __shared__ float bs[CH];
    int tid = threadIdx.x;
    if (tid < CH) bs[tid] = bias[tid];
    __syncthreads();

    int pid = blockIdx.x * 256 + tid;
    int xx = pid & (WW - 1);
    int yy = (pid >> 8) & (HH - 1);

    int nidx[9];
#pragma unroll
    for (int ky = 0; ky < 3; ky++)
#pragma unroll
        for (int kx = 0; kx < 3; kx++) {
            int iy = yy + ky - 1, ix = xx + kx - 1;
            int v = -1;
            if ((unsigned)iy < (unsigned)HH && (unsigned)ix < (unsigned)WW)
                v = __ldg(g_idx + pid + (ky - 1) * WW + (kx - 1));
            nidx[ky * 3 + kx] = v;
        }

    unsigned long long acc[16];
#pragma unroll
    for (int m = 0; m < 16; m++) acc[m] = pack2(bs[2 * m], bs[2 * m + 1]);

#pragma unroll
    for (int t = 0; t < 9; t++) {
        if (nidx[t] < 0) continue;
        const ulonglong2* tp = (const ulonglong2*)(g_T + (size_t)(t * NCODES + nidx[t]) * CH);
#pragma unroll
        for (int q = 0; q < 8; q++) {
            ulonglong2 v = __ldg(tp + q);
            fadd2(acc[2 * q], v.x);
            fadd2(acc[2 * q + 1], v.y);
        }
    }

    float4* op = (float4*)(g_h + (size_t)pid * CH);
#pragma unroll
    for (int q = 0; q < 8; q++) {
        float a, b, c, d;
        unpack2(a, b, acc[2 * q]);
        unpack2(c, d, acc[2 * q + 1]);
        float4 o;
        o.x = fmaxf(a, 0.f); o.y = fmaxf(b, 0.f);
        o.z = fmaxf(c, 0.f); o.w = fmaxf(d, 0.f);
        op[q] = o;
    }
}

// ---------- blend (step 0, general, 1 px/thread — R14 proven config) ----------
__global__ __launch_bounds__(256) void blend_kernel(
    const float* __restrict__ w2g, const float* __restrict__ b2g,
    const float* __restrict__ wtg, const float* __restrict__ btg)
{
    __shared__ __align__(16) float w2t[CH * CH];  // [ic][oc]
    __shared__ __align__(16) float wtt[CH * CH];
    __shared__ float b2s[CH], bts[CH];
    int tid = threadIdx.x;
    for (int i = tid; i < CH * CH; i += 256) {
        int oc = i & 31, ic = i >> 5;
        w2t[i] = w2g[oc * CH + ic];
        wtt[i] = wtg[oc * CH + ic];
    }
    if (tid < CH) { b2s[tid] = b2g[tid]; bts[tid] = btg[tid]; }
    __syncthreads();

    int pid = blockIdx.x * 256 + tid;
    const float4* hp4 = (const float4*)(g_h + (size_t)pid * CH);
    const float4* sp4 = (const float4*)(g_state + (size_t)pid * CH);

    unsigned long long dacc[16], tacc[16];
#pragma unroll
    for (int q = 0; q < 16; q++) {
        dacc[q] = pack2(b2s[2 * q], b2s[2 * q + 1]);
        tacc[q] = pack2(bts[2 * q], bts[2 * q + 1]);
    }
    const ulonglong2* w2v = (const ulonglong2*)w2t;
    const ulonglong2* wtv = (const ulonglong2*)wtt;
    float sval[CH];
#pragma unroll
    for (int q = 0; q < 8; q++) {
        float4 hv = __ldg(hp4 + q);
        float4 sv = __ldg(sp4 + q);
        sval[4 * q + 0] = sv.x; sval[4 * q + 1] = sv.y;
        sval[4 * q + 2] = sv.z; sval[4 * q + 3] = sv.w;
        float hv4[4] = {hv.x, hv.y, hv.z, hv.w};
        float sv4[4] = {sv.x, sv.y, sv.z, sv.w};
#pragma unroll
        for (int j = 0; j < 4; j++) {
            int ic = q * 4 + j;
            unsigned long long hp = pack2(hv4[j], hv4[j]);
            unsigned long long ss = pack2(sv4[j], sv4[j]);
            const ulonglong2* wr2 = w2v + ic * 8;
            const ulonglong2* wrt = wtv + ic * 8;
#pragma unroll
            for (int p = 0; p < 8; p++) {
                ulonglong2 a = wr2[p];
                ffma2(dacc[2 * p], hp, a.x);
                ffma2(dacc[2 * p + 1], hp, a.y);
                ulonglong2 bm = wrt[p];
                ffma2(tacc[2 * p], ss, bm.x);
                ffma2(tacc[2 * p + 1], ss, bm.y);
            }
        }
    }
    float4* zo = (float4*)(g_h + (size_t)pid * CH);
#pragma unroll
    for (int q = 0; q < 8; q++) {
        float t0, t1, d0, d1, t2, t3, d2, d3;
        unpack2(t0, t1, tacc[2 * q]);
        unpack2(d0, d1, dacc[2 * q]);
        unpack2(t2, t3, tacc[2 * q + 1]);
        unpack2(d2, d3, dacc[2 * q + 1]);
        float4 o;
        o.x = d0 + sigf(t0) * (sval[4 * q + 0] - d0);
        o.y = d1 + sigf(t1) * (sval[4 * q + 1] - d1);
        o.z = d2 + sigf(t2) * (sval[4 * q + 2] - d2);
        o.w = d3 + sigf(t3) * (sval[4 * q + 3] - d3);
        zo[q] = o;
    }
}

// ---------- blend via beta table (steps 1..4), 2 pixels/thread ----------
__global__ __launch_bounds__(256) void blend_idx_kernel(
    const float* __restrict__ w2g, const float* __restrict__ b2g,
    const float* __restrict__ cb)
{
    __shared__ __align__(16) float w2t[CH * CH];  // [ic][oc]
    __shared__ float b2s[CH];
    int tid = threadIdx.x;
    for (int i = tid; i < CH * CH; i += 256) {
        int oc = i & 31, ic = i >> 5;
        w2t[i] = w2g[oc * CH + ic];
    }
    if (tid < CH) b2s[tid] = b2g[tid];
    __syncthreads();

    int p0 = blockIdx.x * 512 + tid;
    int p1 = p0 + 256;
    const float4* h0 = (const float4*)(g_h + (size_t)p0 * CH);
    const float4* h1 = (const float4*)(g_h + (size_t)p1 * CH);

    unsigned long long d0a[16], d1a[16];
#pragma unroll
    for (int q = 0; q < 16; q++) {
        d0a[q] = pack2(b2s[2 * q], b2s[2 * q + 1]);
        d1a[q] = d0a[q];
    }
    const ulonglong2* w2v = (const ulonglong2*)w2t;
#pragma unroll
    for (int q = 0; q < 8; q++) {
        float4 a = __ldg(h0 + q);
        float4 b = __ldg(h1 + q);
        float a4[4] = {a.x, a.y, a.z, a.w};
        float b4[4] = {b.x, b.y, b.z, b.w};
#pragma unroll
        for (int j = 0; j < 4; j++) {
            int ic = q * 4 + j;
            unsigned long long va = pack2(a4[j], a4[j]);
            unsigned long long vb = pack2(b4[j], b4[j]);
            const ulonglong2* wr = w2v + ic * 8;
#pragma unroll
            for (int p = 0; p < 8; p++) {
                ulonglong2 w = wr[p];
                ffma2(d0a[2 * p], va, w.x);
                ffma2(d0a[2 * p + 1], va, w.y);
                ffma2(d1a[2 * p], vb, w.x);
                ffma2(d1a[2 * p + 1], vb, w.y);
            }
        }
    }

    {
        int idx = __ldg(g_idx + p0);
        const float4* bp = (const float4*)(g_B + (size_t)idx * CH);
        const float4* sp = (const float4*)(cb + (size_t)idx * CH);
        float4* zo = (float4*)(g_h + (size_t)p0 * CH);
#pragma unroll
        for (int q = 0; q < 8; q++) {
            float4 be = __ldg(bp + q);
            float4 sv = __ldg(sp + q);
            float e0, e1, e2, e3;
            unpack2(e0, e1, d0a[2 * q]);
            unpack2(e2, e3, d0a[2 * q + 1]);
            float4 o;
            o.x = e0 + be.x * (sv.x - e0);
            o.y = e1 + be.y * (sv.y - e1);
            o.z = e2 + be.z * (sv.z - e2);
            o.w = e3 + be.w * (sv.w - e3);
            zo[q] = o;
        }
    }
    {
        int idx = __ldg(g_idx + p1);
        const float4* bp = (const float4*)(g_B + (size_t)idx * CH);
        const float4* sp = (const float4*)(cb + (size_t)idx * CH);
        float4* zo = (float4*)(g_h + (size_t)p1 * CH);
#pragma unroll
        for (int q = 0; q < 8; q++) {
            float4 be = __ldg(bp + q);
            float4 sv = __ldg(sp + q);
            float e0, e1, e2, e3;
            unpack2(e0, e1, d1a[2 * q]);
            unpack2(e2, e3, d1a[2 * q + 1]);
            float4 o;
            o.x = e0 + be.x * (sv.x - e0);
            o.y = e1 + be.y * (sv.y - e1);
            o.z = e2 + be.z * (sv.z - e2);
            o.w = e3 + be.w * (sv.w - e3);
            zo[q] = o;
        }
    }
}

// ---------- VQ via mma.sync f16 m16n8k16, 3-pass split (hh+lh+hl), B scaled 256 ----------
#define BSTR16 20

__global__ __launch_bounds__(256) void vq_mma_kernel(const float* __restrict__ cb)
{
    __shared__ uint32_t sBh[NCODES * BSTR16];  // hi half2 per (col, k2)
    __shared__ uint32_t sBl[NCODES * BSTR16];  // lo half2
    __shared__ float cn[NCODES];
    int tid = threadIdx.x;

    for (int i = tid; i < NCODES * 16; i += 256) {
        int code = i >> 4, k2 = i & 15;
        const float2 v = __ldg((const float2*)(cb + code * CH + 2 * k2));
        uint32_t hi, lo;
        split_h2(v.x * 256.0f, v.y * 256.0f, hi, lo);
        sBh[code * BSTR16 + k2] = hi;
        sBl[code * BSTR16 + k2] = lo;
    }
    {
        float s = 0.0f;
        const float* cr = cb + tid * CH;
#pragma unroll
        for (int c = 0; c < CH; c++) { float v = __ldg(cr + c); s += v * v; }
        cn[tid] = 128.0f * s;
    }
    __syncthreads();

    int wid = tid >> 5, lid = tid & 31;
    int kq = lid & 3;
    int colb = lid >> 2;

#pragma unroll 1
    for (int tile = 0; tile < 2; tile++) {
        int rbase = blockIdx.x * 512 + tile * 256 + wid * 32 + (lid >> 2);

        uint32_t zh[4][4], zl[4][4];
#pragma unroll
        for (int rr = 0; rr < 4; rr++) {
            const float* z = g_h + (size_t)(rbase + 8 * rr) * CH;
#pragma unroll
            for (int j = 0; j < 4; j++) {
                float2 v = __ldg((const float2*)(z + 8 * j + 2 * kq));
                split_h2(v.x, v.y, zh[rr][j], zl[rr][j]);
            }
        }

        float best[4] = {FLT_MAX, FLT_MAX, FLT_MAX, FLT_MAX};
        int bi[4] = {0, 0, 0, 0};

#pragma unroll 1
        for (int chunk = 0; chunk < 8; chunk++) {
#pragma unroll
            for (int nt = 0; nt < 4; nt++) {
                int col = chunk * 32 + nt * 8 + colb;
                const uint32_t* bhp = sBh + col * BSTR16;
                const uint32_t* blp = sBl + col * BSTR16;
                uint32_t bh0 = bhp[kq],     bh1 = bhp[kq + 4];
                uint32_t bh2 = bhp[kq + 8], bh3 = bhp[kq + 12];
                uint32_t bl0 = blp[kq],     bl1 = blp[kq + 4];
                uint32_t bl2 = blp[kq + 8], bl3 = blp[kq + 12];

                float dA0 = 0.f, dA1 = 0.f, dA2 = 0.f, dA3 = 0.f;
                float dB0 = 0.f, dB1 = 0.f, dB2 = 0.f, dB3 = 0.f;
                mma_f16(dA0, dA1, dA2, dA3, zh[0][0], zh[1][0], zh[0][1], zh[1][1], bh0, bh1);
                mma_f16(dA0, dA1, dA2, dA3, zh[0][2], zh[1][2], zh[0][3], zh[1][3], bh2, bh3);
                mma_f16(dA0, dA1, dA2, dA3, zl[0][0], zl[1][0], zl[0][1], zl[1][1], bh0, bh1);
                mma_f16(dA0, dA1, dA2, dA3, zl[0][2], zl[1][2], zl[0][3], zl[1][3], bh2, bh3);
                mma_f16(dA0, dA1, dA2, dA3, zh[0][0], zh[1][0], zh[0][1], zh[1][1], bl0, bl1);
                mma_f16(dA0, dA1, dA2, dA3, zh[0][2], zh[1][2], zh[0][3], zh[1][3], bl2, bl3);
                mma_f16(dB0, dB1, dB2, dB3, zh[2][0], zh[3][0], zh[2][1], zh[3][1], bh0, bh1);
                mma_f16(dB0, dB1, dB2, dB3, zh[2][2], zh[3][2], zh[2][3], zh[3][3], bh2, bh3);
                mma_f16(dB0, dB1, dB2, dB3, zl[2][0], zl[3][0], zl[2][1], zl[3][1], bh0, bh1);
                mma_f16(dB0, dB1, dB2, dB3, zl[2][2], zl[3][2], zl[2][3], zl[3][3], bh2, bh3);
                mma_f16(dB0, dB1, dB2, dB3, zh[2][0], zh[3][0], zh[2][1], zh[3][1], bl0, bl1);
                mma_f16(dB0, dB1, dB2, dB3, zh[2][2], zh[3][2], zh[2][3], zh[3][3], bl2, bl3);

                int c0 = chunk * 32 + nt * 8 + 2 * kq;
                float cna = cn[c0], cnb = cn[c0 + 1];
                float m;
                m = cna - dA0; if (m < best[0]) { best[0] = m; bi[0] = c0; }
                m = cnb - dA1; if (m < best[0]) { best[0] = m; bi[0] = c0 + 1; }
                m = cna - dA2; if (m < best[1]) { best[1] = m; bi[1] = c0; }
                m = cnb - dA3; if (m < best[1]) { best[1] = m; bi[1] = c0 + 1; }
                m = cna - dB0; if (m < best[2]) { best[2] = m; bi[2] = c0; }
                m = cnb - dB1; if (m < best[2]) { best[2] = m; bi[2] = c0 + 1; }
                m = cna - dB2; if (m < best[3]) { best[3] = m; bi[3] = c0; }
                m = cnb - dB3; if (m < best[3]) { best[3] = m; bi[3] = c0 + 1; }
            }
        }

#pragma unroll
        for (int off = 1; off <= 2; off <<= 1) {
#pragma unroll
            for (int rr = 0; rr < 4; rr++) {
                float ob = __shfl_xor_sync(0xffffffffu, best[rr], off);
                int oi = __shfl_xor_sync(0xffffffffu, bi[rr], off);
                if (ob < best[rr] || (ob == best[rr] && oi < bi[rr])) { best[rr] = ob; bi[rr] = oi; }
            }
        }

        if ((lid & 3) == 0) {
#pragma unroll
            for (int rr = 0; rr < 4; rr++)
                g_idx[rbase + 8 * rr] = bi[rr];
        }
    }
}

// ---------- decoder via LUT ----------
__global__ __launch_bounds__(256) void dec_idx_kernel(float* __restrict__ out)
{
    __shared__ float lut[NCODES];
    lut[threadIdx.x] = g_declut[threadIdx.x];
    __syncthreads();
    int pid = blockIdx.x * 256 + threadIdx.x;
    out[pid] = lut[__ldg(g_idx + pid)];
}

extern "C" void kernel_launch(void* const* d_in, const int* in_sizes, int n_in,
                              void* d_out, int out_size)
{
    const float* x      = (const float*)d_in[0];
    const float* stem_w = (const float*)d_in[1];
    const float* stem_b = (const float*)d_in[2];
    const float* up1_w  = (const float*)d_in[3];
    const float* up1_b  = (const float*)d_in[4];
    const float* up2_w  = (const float*)d_in[5];
    const float* up2_b  = (const float*)d_in[6];
    const float* tau_w  = (const float*)d_in[7];
    const float* tau_b  = (const float*)d_in[8];
    const float* cb     = (const float*)d_in[9];
    const float* dec_w  = (const float*)d_in[10];
    const float* dec_b  = (const float*)d_in[11];

    build_tables_kernel<<<10, 256>>>(up1_w, tau_w, tau_b, cb, dec_w, dec_b);
    stem_kernel<<<NPIX / 256, 256>>>(x, stem_w, stem_b);

    // step 0: general path (state not yet quantized)
    conv3_mma_kernel<<<NPIX / 128, 256>>>(up1_w, up1_b);
    blend_kernel<<<NPIX / 256, 256>>>(up2_w, up2_b, tau_w, tau_b);
    vq_mma_kernel<<<NPIX / 512, 256>>>(cb);

    // steps 1..4: table path (split kernels — fusion loses, see R11)
    for (int t = 1; t < NSTEPS; t++) {
        conv_idx_kernel<<<NPIX / 256, 256>>>(up1_b);
        blend_idx_kernel<<<NPIX / 512, 256>>>(up2_w, up2_b, cb);
        vq_mma_kernel<<<NPIX / 512, 256>>>(cb);
    }
    dec_idx_kernel<<<NPIX / 256, 256>>>((float*)d_out);
}